// round 2
// baseline (speedup 1.0000x reference)
#include <cuda_runtime.h>
#include <math.h>
#include <stdint.h>

#define N_INP 512
#define N_OUTP 512
#define NWL 64
#define NB 256

// 64 MB scratch for drop[i][j][w] (static __device__ array — allocation rules OK)
__device__ float g_drop[(size_t)N_OUTP * N_INP * NWL];

// ---------------------------------------------------------------------------
// Kernel 1: per-ring drop transmission.
// One block = 16 rings. Threads 0..15 compute per-ring constants (in double,
// one-time cost); then all 256 threads each produce one float4 (4 wavelengths).
// denom2 = (1-at*cos)^2 + (at*sin)^2 == 1 - 2*at*cos + at^2  (no sin needed).
// Kerr phase (~2.7e-19 rad) is below fp32 resolution vs O(1) detuning -> skipped.
// ---------------------------------------------------------------------------
__global__ void __launch_bounds__(256) drop_kernel(
        const float* __restrict__ phase_shift,
        const float* __restrict__ coupling) {
    __shared__ double s_base[16];
    __shared__ double s_incr[16];
    __shared__ float s_2at[16], s_A[16], s_coef[16];

    const int tid = threadIdx.x;
    const int kblk = blockIdx.x << 4;

    if (tid < 16) {
        const int k = kblk + tid;
        const double WLMIN = 1.53e-06, WLMAX = 1.57e-06;
        double c    = WLMIN + (WLMAX - WLMIN) * ((double)k / (double)(N_INP * N_OUTP));
        double fsr  = c * c / (4.2 * 2.0 * M_PI * 5e-06);
        double pref = 2.0 * M_PI / fsr;
        s_base[tid] = pref * (WLMIN - c) + (double)phase_shift[k];
        s_incr[tid] = pref * ((WLMAX - WLMIN) / 63.0);
        float kap   = fminf(fmaxf(coupling[k], 0.1f), 0.9f);
        float t     = sqrtf(1.0f - kap * kap);
        float alpha = (float)(1.0 - M_PI / 15000.0);
        float at    = alpha * t;
        s_2at[tid]  = 2.0f * at;
        s_A[tid]    = 1.0f + at * at;
        s_coef[tid] = kap * kap * alpha;
    }
    __syncthreads();

    const int r = tid >> 4;   // ring within block
    const int q = tid & 15;   // wavelength quad
    const double base = s_base[r];
    const double incr = s_incr[r];
    const float twoAt = s_2at[r], A = s_A[r], coef = s_coef[r];

    const int w = q << 2;
    float p0 = (float)(base + incr * (double)(w));
    float p1 = (float)(base + incr * (double)(w + 1));
    float p2 = (float)(base + incr * (double)(w + 2));
    float p3 = (float)(base + incr * (double)(w + 3));

    float4 v;
    v.x = coef / (A - twoAt * cosf(p0));
    v.y = coef / (A - twoAt * cosf(p1));
    v.z = coef / (A - twoAt * cosf(p2));
    v.w = coef / (A - twoAt * cosf(p3));

    *(float4*)&g_drop[(size_t)(kblk + r) * NWL + w] = v;
}

// ---------------------------------------------------------------------------
// Kernel 2: out[b,i,w] = sum_j in[b,j,w] * drop[i,j,w]
// 64 independent GEMMs over w (elementwise in w) -> pack w-pairs and use
// Blackwell packed fma.rn.f32x2 (2x fp32 FMA rate; PTX-only per SASS_QUICKREF).
// CTA tile: 64 b  x 32 i x 8 w. Thread tile: 8 b x 4 i x 1 w-pair.
// Double-buffered smem staging, K-chunks of 8.
// ---------------------------------------------------------------------------
#define BT 64
#define IT 32
#define WT 8
#define KC 8
#define NCHUNK (N_INP / KC)

__device__ __forceinline__ void fma2(unsigned long long& c,
                                     const unsigned long long a,
                                     const unsigned long long b) {
    asm("fma.rn.f32x2 %0, %1, %2, %0;" : "+l"(c) : "l"(a), "l"(b));
}

__global__ void __launch_bounds__(256) gemm_kernel(
        const float* __restrict__ in, float* __restrict__ out) {
    __shared__ float s_in[2 * KC * BT * WT];  // 32 KB
    __shared__ float s_dp[2 * KC * IT * WT];  // 16 KB

    const int tid = threadIdx.x;
    const int w0 = blockIdx.x * WT;
    const int i0 = blockIdx.y * IT;
    const int b0 = blockIdx.z * BT;

    const int tx = tid & 3;          // w-pair index (w offset = tx*2)
    const int ty = (tid >> 2) & 7;   // i-group of 4
    const int tz = tid >> 5;         // b-group of 8

    // Loader mappings (constant per thread).
    // s_in: KC*BT*WT/4 = 1024 float4 slots, 4 per thread.
    const float* gin[4];
    int soin[4];
#pragma unroll
    for (int t = 0; t < 4; t++) {
        int s  = tid + (t << 8);
        int jj = s >> 7;
        int rr = s & 127;
        int b  = rr >> 1;
        int wq = rr & 1;
        gin[t]  = in + ((size_t)(b0 + b) * N_INP + jj) * NWL + w0 + (wq << 2);
        soin[t] = (jj * BT + b) * WT + (wq << 2);
    }
    // s_dp: KC*IT*WT/4 = 512 float4 slots, 2 per thread.
    const float* gdp[2];
    int sodp[2];
#pragma unroll
    for (int t = 0; t < 2; t++) {
        int s  = tid + (t << 8);
        int jj = s >> 6;
        int rr = s & 63;
        int i  = rr >> 1;
        int wq = rr & 1;
        gdp[t]  = g_drop + ((size_t)(i0 + i) * N_INP + jj) * NWL + w0 + (wq << 2);
        sodp[t] = (jj * IT + i) * WT + (wq << 2);
    }

    unsigned long long acc[8][4];
#pragma unroll
    for (int bb = 0; bb < 8; bb++)
#pragma unroll
        for (int ii = 0; ii < 4; ii++) acc[bb][ii] = 0ULL;

    float4 rin[4], rdp[2];
    // Prologue: chunk 0 -> buffer 0
#pragma unroll
    for (int t = 0; t < 4; t++) rin[t] = *(const float4*)gin[t];
#pragma unroll
    for (int t = 0; t < 2; t++) rdp[t] = *(const float4*)gdp[t];
#pragma unroll
    for (int t = 0; t < 4; t++) *(float4*)&s_in[soin[t]] = rin[t];
#pragma unroll
    for (int t = 0; t < 2; t++) *(float4*)&s_dp[sodp[t]] = rdp[t];
    __syncthreads();

    for (int c = 0; c < NCHUNK; c++) {
        if (c + 1 < NCHUNK) {
#pragma unroll
            for (int t = 0; t < 4; t++) { gin[t] += KC * NWL; rin[t] = *(const float4*)gin[t]; }
#pragma unroll
            for (int t = 0; t < 2; t++) { gdp[t] += KC * NWL; rdp[t] = *(const float4*)gdp[t]; }
        }

        const float* pin = s_in + (c & 1) * (KC * BT * WT);
        const float* pdp = s_dp + (c & 1) * (KC * IT * WT);
#pragma unroll
        for (int jj = 0; jj < KC; jj++) {
            unsigned long long a[8], d[4];
#pragma unroll
            for (int bb = 0; bb < 8; bb++)
                a[bb] = *(const unsigned long long*)&pin[(jj * BT + tz * 8 + bb) * WT + (tx << 1)];
#pragma unroll
            for (int ii = 0; ii < 4; ii++)
                d[ii] = *(const unsigned long long*)&pdp[(jj * IT + ty * 4 + ii) * WT + (tx << 1)];
#pragma unroll
            for (int bb = 0; bb < 8; bb++)
#pragma unroll
                for (int ii = 0; ii < 4; ii++)
                    fma2(acc[bb][ii], a[bb], d[ii]);
        }

        if (c + 1 < NCHUNK) {
            const int nb = (c + 1) & 1;
#pragma unroll
            for (int t = 0; t < 4; t++) *(float4*)&s_in[nb * (KC * BT * WT) + soin[t]] = rin[t];
#pragma unroll
            for (int t = 0; t < 2; t++) *(float4*)&s_dp[nb * (KC * IT * WT) + sodp[t]] = rdp[t];
        }
        __syncthreads();
    }

    // Epilogue: 8-byte stores (w-pair aligned)
#pragma unroll
    for (int bb = 0; bb < 8; bb++) {
#pragma unroll
        for (int ii = 0; ii < 4; ii++) {
            size_t o = ((size_t)(b0 + tz * 8 + bb) * N_OUTP + (size_t)(i0 + ty * 4 + ii)) * NWL
                       + w0 + (tx << 1);
            *(unsigned long long*)&out[o] = acc[bb][ii];
        }
    }
}

// ---------------------------------------------------------------------------
extern "C" void kernel_launch(void* const* d_in, const int* in_sizes, int n_in,
                              void* d_out, int out_size) {
    const float* input    = (const float*)d_in[0];  // [256,512,64]
    const float* phase    = (const float*)d_in[1];  // [512,512]
    const float* coupling = (const float*)d_in[2];  // [512,512]
    float* out            = (float*)d_out;          // [256,512,64]

    drop_kernel<<<(N_INP * N_OUTP) / 16, 256>>>(phase, coupling);

    dim3 grid(NWL / WT, N_OUTP / IT, NB / BT);  // (8, 16, 4) = 512 CTAs
    gemm_kernel<<<grid, 256>>>(input, out);
}

// round 4
// speedup vs baseline: 5.5553x; 5.5553x over previous
#include <cuda_runtime.h>
#include <math.h>
#include <stdint.h>

#define NB 256
#define NI 512   // outputs (i)
#define NJ 512   // inputs  (j) -> contraction K
#define NW 64

// Scratch (static device arrays: allocation rules OK)
__device__ float g_inT  [(size_t)NW * NB * NJ];   // [w][b][j]  33.5 MB
__device__ float g_dropT[(size_t)NW * NI * NJ];   // [w][i][j]  67   MB
__device__ float g_outT [(size_t)NW * NB * NI];   // [w][b][i]  33.5 MB

__device__ __forceinline__ float tf32r(float x) {
    uint32_t u; asm("cvt.rna.tf32.f32 %0, %1;" : "=r"(u) : "f"(x));
    return __uint_as_float(u);
}

// ---------------------------------------------------------------------------
// Kernel 1: dropT[w][i][j], tf32-rounded.
// denom2 = (1-at cos)^2 + (at sin)^2 = 1 - 2 at cos + at^2.
// Kerr phase ~2.7e-19 rad: below fp32 resolution vs O(1) phase -> skipped.
// Double only for per-ring base/incr; per-w phase in fp32.
// ---------------------------------------------------------------------------
__global__ void __launch_bounds__(256) dropT_kernel(
        const float* __restrict__ phase_shift,
        const float* __restrict__ coupling) {
    const int j = blockIdx.x * 256 + threadIdx.x;
    const int i = blockIdx.y;
    const int k = i * NJ + j;

    const double WLMIN = 1.53e-06, WLMAX = 1.57e-06;
    double c    = WLMIN + (WLMAX - WLMIN) * ((double)k / (double)(NI * NJ));
    // 2*pi/fsr = 4*pi^2 * n_group * R / c^2
    double pref = (4.0 * M_PI * M_PI * 4.2 * 5e-06) / (c * c);
    const float base = (float)(pref * (WLMIN - c)) + phase_shift[k];
    const float dphi = (float)(pref * ((WLMAX - WLMIN) / 63.0));

    float kap = fminf(fmaxf(coupling[k], 0.1f), 0.9f);
    float t   = sqrtf(1.0f - kap * kap);
    const float alpha = (float)(1.0 - M_PI / 15000.0);
    float at  = alpha * t;
    const float A2    = 1.0f + at * at;
    const float twoAt = 2.0f * at;
    const float coef  = kap * kap * alpha;

    float* dst = g_dropT + (size_t)i * NJ + j;
#pragma unroll 4
    for (int w = 0; w < NW; w++) {
        float ph = fmaf((float)w, dphi, base);
        float d  = __fdividef(coef, A2 - twoAt * cosf(ph));
        dst[(size_t)w * NI * NJ] = tf32r(d);
    }
}

// ---------------------------------------------------------------------------
// Kernel 2: transpose input [b][j][w] -> inT[w][b][j], tf32-rounded.
// ---------------------------------------------------------------------------
__global__ void __launch_bounds__(256) tin_kernel(const float* __restrict__ in) {
    __shared__ float s[32][65];
    const int b  = blockIdx.y;
    const int j0 = blockIdx.x * 32;
    const int t  = threadIdx.x;

    {   // load 32 j-rows x 64 w, coalesced 256B per row
        int r = t >> 3, wq = (t & 7) * 8;
        const float4* src = (const float4*)(in + ((size_t)b * NJ + j0 + r) * NW + wq);
        float4 v0 = src[0], v1 = src[1];
        s[r][wq + 0] = v0.x; s[r][wq + 1] = v0.y; s[r][wq + 2] = v0.z; s[r][wq + 3] = v0.w;
        s[r][wq + 4] = v1.x; s[r][wq + 5] = v1.y; s[r][wq + 6] = v1.z; s[r][wq + 7] = v1.w;
    }
    __syncthreads();
    {   // write 64 w-rows x 32 j
        int w = t >> 2, jg = (t & 3) * 8;
        float* dst = g_inT + ((size_t)w * NB + b) * NJ + j0 + jg;
        float4 o0, o1;
        o0.x = tf32r(s[jg + 0][w]); o0.y = tf32r(s[jg + 1][w]);
        o0.z = tf32r(s[jg + 2][w]); o0.w = tf32r(s[jg + 3][w]);
        o1.x = tf32r(s[jg + 4][w]); o1.y = tf32r(s[jg + 5][w]);
        o1.z = tf32r(s[jg + 6][w]); o1.w = tf32r(s[jg + 7][w]);
        ((float4*)dst)[0] = o0; ((float4*)dst)[1] = o1;
    }
}

// ---------------------------------------------------------------------------
// Kernel 3: mma.sync (tf32 m16n8k8) GEMM per w-plane.
// D[b][i] = sum_j inT[w][b][j] * dropT[w][i][j]
// A [M,K] row-major (K-major), B [N,K] -> col-major K x N: both j-contiguous.
// CTA tile 128x128, Kc=32, double-buffered cp.async, smem rows padded to 36 f.
// 8 warps, warp tile 64x32 = 4x4 m16n8 tiles.
// ---------------------------------------------------------------------------
#define TM 128
#define TN 128
#define KC 32
#define NCH (NJ / KC)          // 16
#define RS 36                  // smem row stride in floats (144 B)
#define TILE_B (128 * RS * 4)  // 18432 bytes
#define SMEM_REQ (4 * TILE_B)  // 73728 bytes

#define CPA(s, g) asm volatile("cp.async.cg.shared.global [%0], [%1], 16;" :: "r"(s), "l"(g))

#define MMA_TF32(c, a, b) \
    asm volatile("mma.sync.aligned.m16n8k8.row.col.f32.tf32.tf32.f32 " \
        "{%0,%1,%2,%3}, {%4,%5,%6,%7}, {%8,%9}, {%0,%1,%2,%3};" \
        : "+f"((c)[0]), "+f"((c)[1]), "+f"((c)[2]), "+f"((c)[3]) \
        : "r"((a)[0]), "r"((a)[1]), "r"((a)[2]), "r"((a)[3]), \
          "r"((b)[0]), "r"((b)[1]))

static __device__ __forceinline__ uint32_t smem_u32(const void* p) {
    uint32_t a;
    asm("{ .reg .u64 t; cvta.to.shared.u64 t, %1; cvt.u32.u64 %0, t; }" : "=r"(a) : "l"(p));
    return a;
}

__global__ void __launch_bounds__(256, 2) gemm_kernel() {
    extern __shared__ float smem[];          // [A0|A1|B0|B1], each 128*RS floats
    const uint32_t sbase = smem_u32(smem);

    const int tid = threadIdx.x;
    const int w   = blockIdx.x;
    const int b0  = blockIdx.y * TM;
    const int i0  = blockIdx.z * TN;

    // ---- loaders: per thread 4 x 16B for A and for B per chunk ----
    const float* gA[4]; const float* gB[4]; uint32_t sOff[4];
#pragma unroll
    for (int t = 0; t < 4; t++) {
        int idx  = tid + (t << 8);     // 0..1023
        int row  = idx >> 3;           // 0..127
        int word = idx & 7;            // 16B word within 128B of data
        gA[t] = g_inT   + ((size_t)w * NB + b0 + row) * NJ + word * 4;
        gB[t] = g_dropT + ((size_t)w * NI + i0 + row) * NJ + word * 4;
        sOff[t] = (uint32_t)(row * RS * 4 + word * 16);
    }

    // prologue: chunk 0 -> buf0, chunk 1 -> buf1
#pragma unroll
    for (int t = 0; t < 4; t++) {
        CPA(sbase + sOff[t],              gA[t]);
        CPA(sbase + 2 * TILE_B + sOff[t], gB[t]);
    }
    asm volatile("cp.async.commit_group;" ::: "memory");
#pragma unroll
    for (int t = 0; t < 4; t++) {
        CPA(sbase + TILE_B + sOff[t],     gA[t] + KC);
        CPA(sbase + 3 * TILE_B + sOff[t], gB[t] + KC);
    }
    asm volatile("cp.async.commit_group;" ::: "memory");
#pragma unroll
    for (int t = 0; t < 4; t++) { gA[t] += 2 * KC; gB[t] += 2 * KC; }

    // ---- fragment indexing ----
    const int lane = tid & 31, wid = tid >> 5;
    const int g = lane >> 2, q = lane & 3;
    const int wm = (wid >> 2) * 64;    // warp m-offset (0/64)
    const int wn = (wid & 3) * 32;     // warp n-offset (0..96)

    float acc[4][4][4];
#pragma unroll
    for (int mt = 0; mt < 4; mt++)
#pragma unroll
        for (int nt = 0; nt < 4; nt++)
#pragma unroll
            for (int r = 0; r < 4; r++) acc[mt][nt][r] = 0.0f;

    for (int c = 0; c < NCH; c++) {
        if (c < NCH - 1) asm volatile("cp.async.wait_group 1;" ::: "memory");
        else             asm volatile("cp.async.wait_group 0;" ::: "memory");
        __syncthreads();

        const int par = c & 1;
        const float* pA = smem + par * (128 * RS);
        const float* pB = smem + (2 + par) * (128 * RS);

#pragma unroll
        for (int ks = 0; ks < 4; ks++) {
            const int k0 = ks * 8;
            uint32_t a[4][4], b[4][2];
#pragma unroll
            for (int mt = 0; mt < 4; mt++) {
                const float* r0 = pA + (wm + mt * 16 + g) * RS + k0 + q;
                a[mt][0] = __float_as_uint(r0[0]);
                a[mt][1] = __float_as_uint(r0[8 * RS]);
                a[mt][2] = __float_as_uint(r0[4]);
                a[mt][3] = __float_as_uint(r0[8 * RS + 4]);
            }
#pragma unroll
            for (int nt = 0; nt < 4; nt++) {
                const float* rb = pB + (wn + nt * 8 + g) * RS + k0 + q;
                b[nt][0] = __float_as_uint(rb[0]);
                b[nt][1] = __float_as_uint(rb[4]);
            }
#pragma unroll
            for (int mt = 0; mt < 4; mt++)
#pragma unroll
                for (int nt = 0; nt < 4; nt++)
                    MMA_TF32(acc[mt][nt], a[mt], b[nt]);
        }

        if (c + 2 < NCH) {
            __syncthreads();   // all warps done reading buf[par]
#pragma unroll
            for (int t = 0; t < 4; t++) {
                CPA(sbase + par * TILE_B + sOff[t],       gA[t]);
                CPA(sbase + (2 + par) * TILE_B + sOff[t], gB[t]);
                gA[t] += KC; gB[t] += KC;
            }
            asm volatile("cp.async.commit_group;" ::: "memory");
        }
    }

    // ---- epilogue: acc -> g_outT[w][b][i] (8B stores, even columns) ----
#pragma unroll
    for (int mt = 0; mt < 4; mt++) {
        const int row = b0 + wm + mt * 16 + g;
#pragma unroll
        for (int nt = 0; nt < 4; nt++) {
            const int col = i0 + wn + nt * 8 + 2 * q;
            float2 v0 = make_float2(acc[mt][nt][0], acc[mt][nt][1]);
            float2 v1 = make_float2(acc[mt][nt][2], acc[mt][nt][3]);
            *(float2*)&g_outT[((size_t)w * NB + row)     * NI + col] = v0;
            *(float2*)&g_outT[((size_t)w * NB + row + 8) * NI + col] = v1;
        }
    }
}

// ---------------------------------------------------------------------------
// Kernel 4: transpose outT[w][b][i] -> out[b][i][w]
// ---------------------------------------------------------------------------
__global__ void __launch_bounds__(256) tout_kernel(float* __restrict__ out) {
    __shared__ float s[32][65];
    const int b  = blockIdx.y;
    const int i0 = blockIdx.x * 32;
    const int t  = threadIdx.x;

    {   // load 64 w-rows x 32 i
        int w = t >> 2, ig = (t & 3) * 8;
        const float4* src = (const float4*)(g_outT + ((size_t)w * NB + b) * NI + i0 + ig);
        float4 v0 = src[0], v1 = src[1];
        s[ig + 0][w] = v0.x; s[ig + 1][w] = v0.y; s[ig + 2][w] = v0.z; s[ig + 3][w] = v0.w;
        s[ig + 4][w] = v1.x; s[ig + 5][w] = v1.y; s[ig + 6][w] = v1.z; s[ig + 7][w] = v1.w;
    }
    __syncthreads();
    {   // write 32 i-rows x 64 w (256B per row)
        int r = t >> 3, wq = (t & 7) * 8;
        float* dst = out + ((size_t)b * NI + i0 + r) * NW + wq;
        float4 o0, o1;
        o0.x = s[r][wq + 0]; o0.y = s[r][wq + 1]; o0.z = s[r][wq + 2]; o0.w = s[r][wq + 3];
        o1.x = s[r][wq + 4]; o1.y = s[r][wq + 5]; o1.z = s[r][wq + 6]; o1.w = s[r][wq + 7];
        ((float4*)dst)[0] = o0; ((float4*)dst)[1] = o1;
    }
}

// ---------------------------------------------------------------------------
extern "C" void kernel_launch(void* const* d_in, const int* in_sizes, int n_in,
                              void* d_out, int out_size) {
    const float* input    = (const float*)d_in[0];  // [256,512,64]
    const float* phase    = (const float*)d_in[1];  // [512,512]
    const float* coupling = (const float*)d_in[2];  // [512,512]
    float* out            = (float*)d_out;          // [256,512,64]

    cudaFuncSetAttribute(gemm_kernel, cudaFuncAttributeMaxDynamicSharedMemorySize, SMEM_REQ);

    dropT_kernel<<<dim3(NJ / 256, NI), 256>>>(phase, coupling);
    tin_kernel  <<<dim3(NJ / 32, NB), 256>>>(input);
    gemm_kernel <<<dim3(NW, NB / TM, NI / TN), 256, SMEM_REQ>>>();
    tout_kernel <<<dim3(NI / 32, NB), 256>>>(out);
}